// round 1
// baseline (speedup 1.0000x reference)
#include <cuda_runtime.h>
#include <cuda_bf16.h>
#include <cstdint>

// Problem constants
#define NNODES 50000
#define NEDGES 600000
#define IN_DIM 256
#define NH     4
#define HD     128
#define FDIM   (NH*HD)     // 512
#define NEG_SLOPE 0.2f

// ---------------- scratch (static __device__ — no allocations allowed) ----------------
__device__ float g_T[(size_t)NNODES * FDIM];     // h = x@W (per layer)    102.4 MB
__device__ float g_R[(size_t)NNODES * FDIM];     // rst accumulator        102.4 MB
__device__ float g_EX[(size_t)NEDGES * NH];      // exp(e) per edge/head     9.6 MB
__device__ float g_el[NNODES * NH];
__device__ float g_er[NNODES * NH];
__device__ float g_denom[NNODES * NH];

// ---------------- zero fill ----------------
__global__ void zero_kernel(float* p, size_t n4) {  // n4 = count of float4
    size_t i = (size_t)blockIdx.x * blockDim.x + threadIdx.x;
    if (i < n4) ((float4*)p)[i] = make_float4(0.f, 0.f, 0.f, 0.f);
}

// ---------------- SGEMM: C[M,512] = A[M,K] @ B[K,512], optional relu(A) ----------------
// 128x128 tile, BK=8, 256 threads, 8x8 microtile.
template <bool RELU_A>
__global__ __launch_bounds__(256) void sgemm_kernel(const float* __restrict__ A,
                                                    const float* __restrict__ B,
                                                    float* __restrict__ C,
                                                    int M, int K) {
    const int N = FDIM;  // 512
    __shared__ float As[8][128];
    __shared__ float Bs[8][128];

    int tid = threadIdx.x;
    int row0 = blockIdx.y * 128;
    int col0 = blockIdx.x * 128;

    int aRow = tid >> 1;           // 0..127
    int aCol = (tid & 1) * 4;      // 0 or 4
    int bRow = tid >> 5;           // 0..7
    int bCol = (tid & 31) * 4;     // 0..124

    int tx = tid & 15;             // 0..15 -> 8 cols each
    int ty = tid >> 4;             // 0..15 -> 8 rows each

    float acc[8][8];
#pragma unroll
    for (int i = 0; i < 8; i++)
#pragma unroll
        for (int j = 0; j < 8; j++) acc[i][j] = 0.f;

    for (int k0 = 0; k0 < K; k0 += 8) {
        float4 av = make_float4(0.f, 0.f, 0.f, 0.f);
        int gr = row0 + aRow;
        if (gr < M) av = *(const float4*)(A + (size_t)gr * K + k0 + aCol);
        if (RELU_A) {
            av.x = fmaxf(av.x, 0.f); av.y = fmaxf(av.y, 0.f);
            av.z = fmaxf(av.z, 0.f); av.w = fmaxf(av.w, 0.f);
        }
        As[aCol + 0][aRow] = av.x;
        As[aCol + 1][aRow] = av.y;
        As[aCol + 2][aRow] = av.z;
        As[aCol + 3][aRow] = av.w;

        float4 bv = *(const float4*)(B + (size_t)(k0 + bRow) * N + col0 + bCol);
        *(float4*)&Bs[bRow][bCol] = bv;

        __syncthreads();

#pragma unroll
        for (int k = 0; k < 8; k++) {
            float a[8], b[8];
#pragma unroll
            for (int i = 0; i < 8; i++) a[i] = As[k][ty * 8 + i];
#pragma unroll
            for (int j = 0; j < 8; j++) b[j] = Bs[k][tx * 8 + j];
#pragma unroll
            for (int i = 0; i < 8; i++)
#pragma unroll
                for (int j = 0; j < 8; j++) acc[i][j] = fmaf(a[i], b[j], acc[i][j]);
        }
        __syncthreads();
    }

#pragma unroll
    for (int i = 0; i < 8; i++) {
        int r = row0 + ty * 8 + i;
        if (r < M) {
            float* cp = C + (size_t)r * N + col0 + tx * 8;
            *(float4*)cp       = make_float4(acc[i][0], acc[i][1], acc[i][2], acc[i][3]);
            *(float4*)(cp + 4) = make_float4(acc[i][4], acc[i][5], acc[i][6], acc[i][7]);
        }
    }
}

// ---------------- el/er: per (node, head) dot products ----------------
__global__ void eler_kernel(const float* __restrict__ T,
                            const float* __restrict__ al,
                            const float* __restrict__ ar,
                            float* __restrict__ el, float* __restrict__ er) {
    int warp = (blockIdx.x * blockDim.x + threadIdx.x) >> 5;
    int lane = threadIdx.x & 31;
    if (warp >= NNODES * NH) return;
    int n = warp >> 2;
    int h = warp & 3;

    const float4 tv = *(const float4*)(T + (size_t)n * FDIM + h * HD + lane * 4);
    const float4 av = *(const float4*)(al + h * HD + lane * 4);
    const float4 rv = *(const float4*)(ar + h * HD + lane * 4);

    float sl = tv.x * av.x + tv.y * av.y + tv.z * av.z + tv.w * av.w;
    float sr = tv.x * rv.x + tv.y * rv.y + tv.z * rv.z + tv.w * rv.w;
#pragma unroll
    for (int o = 16; o > 0; o >>= 1) {
        sl += __shfl_xor_sync(0xFFFFFFFFu, sl, o);
        sr += __shfl_xor_sync(0xFFFFFFFFu, sr, o);
    }
    if (lane == 0) { el[warp] = sl; er[warp] = sr; }
}

// ---------------- edge pass 1: e -> leaky_relu -> exp, accumulate denom ----------------
// NOTE: segment-max is skipped: softmax is shift-invariant and |e| is O(1) here,
// so exp never overflows. Mathematically identical to the reference.
__device__ __forceinline__ float lrelu_exp(float v) {
    v = v > 0.f ? v : NEG_SLOPE * v;
    return __expf(v);
}

__global__ void edge1_kernel(const int* __restrict__ src, const int* __restrict__ dst,
                             const float* __restrict__ el, const float* __restrict__ er,
                             float* __restrict__ EX, float* __restrict__ denom) {
    int e = blockIdx.x * blockDim.x + threadIdx.x;
    if (e >= NEDGES) return;
    int s = src[e], t = dst[e];
    float4 l = *(const float4*)(el + (size_t)s * NH);
    float4 r = *(const float4*)(er + (size_t)t * NH);
    float4 o;
    o.x = lrelu_exp(l.x + r.x);
    o.y = lrelu_exp(l.y + r.y);
    o.z = lrelu_exp(l.z + r.z);
    o.w = lrelu_exp(l.w + r.w);
    *(float4*)(EX + (size_t)e * NH) = o;
    float* dn = denom + (size_t)t * NH;
    atomicAdd(dn + 0, o.x);
    atomicAdd(dn + 1, o.y);
    atomicAdd(dn + 2, o.z);
    atomicAdd(dn + 3, o.w);
}

// ---------------- edge pass 2: rst[dst] += alpha * h[src]  (one warp per edge) ----------------
__global__ __launch_bounds__(256) void edge2_kernel(const int* __restrict__ src,
                                                    const int* __restrict__ dst,
                                                    const float* __restrict__ EX,
                                                    const float* __restrict__ denom,
                                                    const float* __restrict__ T,
                                                    float* __restrict__ R) {
    int gwarp = (blockIdx.x * blockDim.x + threadIdx.x) >> 5;
    int lane = threadIdx.x & 31;
    if (gwarp >= NEDGES) return;
    int s = __ldg(src + gwarp);
    int t = __ldg(dst + gwarp);
    float4 ex = *(const float4*)(EX + (size_t)gwarp * NH);
    float4 dn = *(const float4*)(denom + (size_t)t * NH);
    float alpha[4] = { ex.x / dn.x, ex.y / dn.y, ex.z / dn.z, ex.w / dn.w };

    const float* Ts = T + (size_t)s * FDIM;
    float* Rt = R + (size_t)t * FDIM;
#pragma unroll
    for (int c = 0; c < 4; c++) {
        int off = c * HD + lane * 4;
        float4 hv = *(const float4*)(Ts + off);
        float a = alpha[c];
        atomicAdd(Rt + off + 0, a * hv.x);
        atomicAdd(Rt + off + 1, a * hv.y);
        atomicAdd(Rt + off + 2, a * hv.z);
        atomicAdd(Rt + off + 3, a * hv.w);
    }
}

// ---------------- final: out[n,d] = mean_h relu(rst[n,h,d]) ----------------
__global__ void mean_kernel(const float* __restrict__ R, float* __restrict__ out) {
    int i = blockIdx.x * blockDim.x + threadIdx.x;
    if (i >= NNODES * HD) return;
    int n = i >> 7;
    int d = i & 127;
    const float* r = R + (size_t)n * FDIM + d;
    float v = fmaxf(r[0], 0.f) + fmaxf(r[HD], 0.f) + fmaxf(r[2 * HD], 0.f) + fmaxf(r[3 * HD], 0.f);
    out[i] = 0.25f * v;
}

// ---------------- launch ----------------
extern "C" void kernel_launch(void* const* d_in, const int* in_sizes, int n_in,
                              void* d_out, int out_size) {
    const float* x   = (const float*)d_in[0];
    const int*   src = (const int*)d_in[1];
    const int*   dst = (const int*)d_in[2];
    const float* W0  = (const float*)d_in[3];
    const float* al0 = (const float*)d_in[4];
    const float* ar0 = (const float*)d_in[5];
    const float* W1  = (const float*)d_in[6];
    const float* al1 = (const float*)d_in[7];
    const float* ar1 = (const float*)d_in[8];
    float* out = (float*)d_out;

    float *T, *R, *EX, *el, *er, *denom;
    cudaGetSymbolAddress((void**)&T, g_T);
    cudaGetSymbolAddress((void**)&R, g_R);
    cudaGetSymbolAddress((void**)&EX, g_EX);
    cudaGetSymbolAddress((void**)&el, g_el);
    cudaGetSymbolAddress((void**)&er, g_er);
    cudaGetSymbolAddress((void**)&denom, g_denom);

    const size_t bigN4 = (size_t)NNODES * FDIM / 4;   // R zero (float4 count)
    const size_t dnN4  = (size_t)NNODES * NH / 4;     // denom zero

    dim3 gemmGrid(FDIM / 128, (NNODES + 127) / 128);
    int elerBlocks  = (NNODES * NH + 7) / 8;                 // 8 warps/block
    int edge1Blocks = (NEDGES + 255) / 256;
    int edge2Blocks = (NEDGES + 7) / 8;                      // 8 warps/block
    int meanBlocks  = (NNODES * HD + 255) / 256;

    // ---------------- layer 0 ----------------
    zero_kernel<<<(unsigned)((bigN4 + 255) / 256), 256>>>(R, bigN4);
    zero_kernel<<<(unsigned)((dnN4 + 255) / 256), 256>>>(denom, dnN4);
    sgemm_kernel<false><<<gemmGrid, 256>>>(x, W0, T, NNODES, IN_DIM);
    eler_kernel<<<elerBlocks, 256>>>(T, al0, ar0, el, er);
    edge1_kernel<<<edge1Blocks, 256>>>(src, dst, el, er, EX, denom);
    edge2_kernel<<<edge2Blocks, 256>>>(src, dst, EX, denom, T, R);

    // ---------------- layer 1 ----------------
    // GEMM reads relu(R) first, then R is re-zeroed for the next accumulation.
    sgemm_kernel<true><<<gemmGrid, 256>>>(R, W1, T, NNODES, FDIM);
    zero_kernel<<<(unsigned)((bigN4 + 255) / 256), 256>>>(R, bigN4);
    zero_kernel<<<(unsigned)((dnN4 + 255) / 256), 256>>>(denom, dnN4);
    eler_kernel<<<elerBlocks, 256>>>(T, al1, ar1, el, er);
    edge1_kernel<<<edge1Blocks, 256>>>(src, dst, el, er, EX, denom);
    edge2_kernel<<<edge2Blocks, 256>>>(src, dst, EX, denom, T, R);

    mean_kernel<<<meanBlocks, 256>>>(R, out);
}

// round 4
// speedup vs baseline: 1.2222x; 1.2222x over previous
#include <cuda_runtime.h>
#include <cuda_bf16.h>
#include <cstdint>

// Problem constants
#define NNODES 50000
#define NEDGES 600000
#define IN_DIM 256
#define NH     4
#define HD     128
#define FDIM   (NH*HD)     // 512
#define NEG_SLOPE 0.2f

// ---------------- scratch (static __device__ — no allocations allowed) ----------------
__device__ float g_T[(size_t)NNODES * FDIM];     // h = x@W (per layer)
__device__ float g_R[(size_t)NNODES * FDIM];     // rst accumulator
__device__ float g_EX[(size_t)NEDGES * NH];      // exp(e) per edge/head
__device__ float g_el[NNODES * NH];
__device__ float g_er[NNODES * NH];
__device__ float g_denom[NNODES * NH];
__device__ __nv_bfloat16 g_Ahi[(size_t)NNODES * FDIM];
__device__ __nv_bfloat16 g_Alo[(size_t)NNODES * FDIM];
__device__ __nv_bfloat16 g_Whi[(size_t)FDIM * FDIM];   // W^T [N=512, K] bf16 hi
__device__ __nv_bfloat16 g_Wlo[(size_t)FDIM * FDIM];   // W^T [N=512, K] bf16 lo

// ---------------- zero fill ----------------
__global__ void zero_kernel(float* p, size_t n4) {
    size_t i = (size_t)blockIdx.x * blockDim.x + threadIdx.x;
    if (i < n4) ((float4*)p)[i] = make_float4(0.f, 0.f, 0.f, 0.f);
}

// ---------------- fp32 -> bf16 hi/lo split (element-wise, optional relu) ----------------
__global__ void convA_kernel(const float* __restrict__ in,
                             __nv_bfloat16* __restrict__ hi,
                             __nv_bfloat16* __restrict__ lo,
                             size_t n4, int relu) {
    size_t i = (size_t)blockIdx.x * blockDim.x + threadIdx.x;
    if (i >= n4) return;
    float4 v = ((const float4*)in)[i];
    if (relu) {
        v.x = fmaxf(v.x, 0.f); v.y = fmaxf(v.y, 0.f);
        v.z = fmaxf(v.z, 0.f); v.w = fmaxf(v.w, 0.f);
    }
    __nv_bfloat16 h0 = __float2bfloat16_rn(v.x), h1 = __float2bfloat16_rn(v.y);
    __nv_bfloat16 h2 = __float2bfloat16_rn(v.z), h3 = __float2bfloat16_rn(v.w);
    __nv_bfloat16 l0 = __float2bfloat16_rn(v.x - __bfloat162float(h0));
    __nv_bfloat16 l1 = __float2bfloat16_rn(v.y - __bfloat162float(h1));
    __nv_bfloat16 l2 = __float2bfloat16_rn(v.z - __bfloat162float(h2));
    __nv_bfloat16 l3 = __float2bfloat16_rn(v.w - __bfloat162float(h3));
    ((__nv_bfloat162*)hi)[i * 2 + 0] = __nv_bfloat162(h0, h1);
    ((__nv_bfloat162*)hi)[i * 2 + 1] = __nv_bfloat162(h2, h3);
    ((__nv_bfloat162*)lo)[i * 2 + 0] = __nv_bfloat162(l0, l1);
    ((__nv_bfloat162*)lo)[i * 2 + 1] = __nv_bfloat162(l2, l3);
}

// ---------------- W[K,512] -> W^T[512,K] bf16 hi/lo ----------------
__global__ void convW_kernel(const float* __restrict__ W,
                             __nv_bfloat16* __restrict__ hi,
                             __nv_bfloat16* __restrict__ lo, int K) {
    int idx = blockIdx.x * blockDim.x + threadIdx.x;
    if (idx >= FDIM * K) return;
    int n = idx / K, k = idx - n * K;
    float v = W[(size_t)k * FDIM + n];
    __nv_bfloat16 h = __float2bfloat16_rn(v);
    hi[idx] = h;
    lo[idx] = __float2bfloat16_rn(v - __bfloat162float(h));
}

// ---------------- HMMA GEMM: C[M,512] = A[M,K] @ W^T(B),  bf16 3-term split ----------------
// mma.sync.aligned.m16n8k16.row.col.f32.bf16.bf16.f32  (works on plain sm_103 target).
// CTA tile 128x128, BK=32, 8 warps in 4x2 grid (warp tile 32 rows x 64 cols).
#define MMA_BF16(d, a, b)                                                            \
    asm volatile("mma.sync.aligned.m16n8k16.row.col.f32.bf16.bf16.f32 "              \
        "{%0,%1,%2,%3}, {%4,%5,%6,%7}, {%8,%9}, {%0,%1,%2,%3};"                      \
        : "+f"((d)[0]), "+f"((d)[1]), "+f"((d)[2]), "+f"((d)[3])                     \
        : "r"((a)[0]), "r"((a)[1]), "r"((a)[2]), "r"((a)[3]),                        \
          "r"((b)[0]), "r"((b)[1]))

template <int K>
__global__ __launch_bounds__(256) void hmma_gemm(const __nv_bfloat16* __restrict__ Ahi,
                                                 const __nv_bfloat16* __restrict__ Alo,
                                                 const __nv_bfloat16* __restrict__ Bhi,
                                                 const __nv_bfloat16* __restrict__ Blo,
                                                 float* __restrict__ C, int M) {
    __shared__ __nv_bfloat16 sAh[128][40];
    __shared__ __nv_bfloat16 sAl[128][40];
    __shared__ __nv_bfloat16 sBh[128][40];
    __shared__ __nv_bfloat16 sBl[128][40];

    int tid = threadIdx.x;
    int lane = tid & 31;
    int wid = tid >> 5;
    int wr = wid & 3;        // warp row (0..3): 32 M-rows each
    int wc = wid >> 2;       // warp col (0..1): 64 N-cols each
    int gr4 = lane >> 2;     // 0..7
    int tig = lane & 3;      // 0..3

    int row0 = blockIdx.y * 128;
    int col0 = blockIdx.x * 128;

    float acc[2][8][4];
#pragma unroll
    for (int mt = 0; mt < 2; mt++)
#pragma unroll
        for (int nt = 0; nt < 8; nt++)
#pragma unroll
            for (int q = 0; q < 4; q++) acc[mt][nt][q] = 0.f;

#pragma unroll 1
    for (int kt = 0; kt < K / 32; kt++) {
        int k0 = kt * 32;
        __syncthreads();
        // Load 128x32 bf16 tiles (hi+lo for A and B). 512 chunks of 8 bf16 per buffer.
#pragma unroll
        for (int j = 0; j < 2; j++) {
            int idx = tid + j * 256;
            int r = idx >> 2, c = (idx & 3) * 8;
            int gr = row0 + r;
            uint4 vh = make_uint4(0u, 0u, 0u, 0u), vl = vh;
            if (gr < M) {
                vh = *(const uint4*)(Ahi + (size_t)gr * K + k0 + c);
                vl = *(const uint4*)(Alo + (size_t)gr * K + k0 + c);
            }
            *(uint4*)&sAh[r][c] = vh;
            *(uint4*)&sAl[r][c] = vl;
            *(uint4*)&sBh[r][c] = *(const uint4*)(Bhi + (size_t)(col0 + r) * K + k0 + c);
            *(uint4*)&sBl[r][c] = *(const uint4*)(Blo + (size_t)(col0 + r) * K + k0 + c);
        }
        __syncthreads();

#pragma unroll
        for (int ks = 0; ks < 2; ks++) {
            int kb = ks * 16;
            uint32_t ah[2][4], al[2][4];
#pragma unroll
            for (int mt = 0; mt < 2; mt++) {
                int mr = wr * 32 + mt * 16 + gr4;
                ah[mt][0] = *(const uint32_t*)&sAh[mr][kb + tig * 2];
                ah[mt][1] = *(const uint32_t*)&sAh[mr + 8][kb + tig * 2];
                ah[mt][2] = *(const uint32_t*)&sAh[mr][kb + 8 + tig * 2];
                ah[mt][3] = *(const uint32_t*)&sAh[mr + 8][kb + 8 + tig * 2];
                al[mt][0] = *(const uint32_t*)&sAl[mr][kb + tig * 2];
                al[mt][1] = *(const uint32_t*)&sAl[mr + 8][kb + tig * 2];
                al[mt][2] = *(const uint32_t*)&sAl[mr][kb + 8 + tig * 2];
                al[mt][3] = *(const uint32_t*)&sAl[mr + 8][kb + 8 + tig * 2];
            }
#pragma unroll
            for (int nt = 0; nt < 8; nt++) {
                int nc = wc * 64 + nt * 8 + gr4;
                uint32_t bh[2], bl[2];
                bh[0] = *(const uint32_t*)&sBh[nc][kb + tig * 2];
                bh[1] = *(const uint32_t*)&sBh[nc][kb + 8 + tig * 2];
                bl[0] = *(const uint32_t*)&sBl[nc][kb + tig * 2];
                bl[1] = *(const uint32_t*)&sBl[nc][kb + 8 + tig * 2];
#pragma unroll
                for (int mt = 0; mt < 2; mt++) {
                    MMA_BF16(acc[mt][nt], ah[mt], bh);
                    MMA_BF16(acc[mt][nt], ah[mt], bl);
                    MMA_BF16(acc[mt][nt], al[mt], bh);
                }
            }
        }
    }

    // Epilogue
#pragma unroll
    for (int mt = 0; mt < 2; mt++) {
        int r0 = row0 + wr * 32 + mt * 16 + gr4;
#pragma unroll
        for (int nt = 0; nt < 8; nt++) {
            int cc = col0 + wc * 64 + nt * 8 + tig * 2;
            if (r0 < M)
                *(float2*)(C + (size_t)r0 * FDIM + cc) = make_float2(acc[mt][nt][0], acc[mt][nt][1]);
            if (r0 + 8 < M)
                *(float2*)(C + (size_t)(r0 + 8) * FDIM + cc) = make_float2(acc[mt][nt][2], acc[mt][nt][3]);
        }
    }
}

// ---------------- el/er: per (node, head) dot products ----------------
__global__ void eler_kernel(const float* __restrict__ T,
                            const float* __restrict__ al,
                            const float* __restrict__ ar,
                            float* __restrict__ el, float* __restrict__ er) {
    int warp = (blockIdx.x * blockDim.x + threadIdx.x) >> 5;
    int lane = threadIdx.x & 31;
    if (warp >= NNODES * NH) return;
    int n = warp >> 2;
    int h = warp & 3;

    const float4 tv = *(const float4*)(T + (size_t)n * FDIM + h * HD + lane * 4);
    const float4 av = *(const float4*)(al + h * HD + lane * 4);
    const float4 rv = *(const float4*)(ar + h * HD + lane * 4);

    float sl = tv.x * av.x + tv.y * av.y + tv.z * av.z + tv.w * av.w;
    float sr = tv.x * rv.x + tv.y * rv.y + tv.z * rv.z + tv.w * rv.w;
#pragma unroll
    for (int o = 16; o > 0; o >>= 1) {
        sl += __shfl_xor_sync(0xFFFFFFFFu, sl, o);
        sr += __shfl_xor_sync(0xFFFFFFFFu, sr, o);
    }
    if (lane == 0) { el[warp] = sl; er[warp] = sr; }
}

// ---------------- edge pass 1 ----------------
__device__ __forceinline__ float lrelu_exp(float v) {
    v = v > 0.f ? v : NEG_SLOPE * v;
    return __expf(v);
}

__global__ void edge1_kernel(const int* __restrict__ src, const int* __restrict__ dst,
                             const float* __restrict__ el, const float* __restrict__ er,
                             float* __restrict__ EX, float* __restrict__ denom) {
    int e = blockIdx.x * blockDim.x + threadIdx.x;
    if (e >= NEDGES) return;
    int s = src[e], t = dst[e];
    float4 l = *(const float4*)(el + (size_t)s * NH);
    float4 r = *(const float4*)(er + (size_t)t * NH);
    float4 o;
    o.x = lrelu_exp(l.x + r.x);
    o.y = lrelu_exp(l.y + r.y);
    o.z = lrelu_exp(l.z + r.z);
    o.w = lrelu_exp(l.w + r.w);
    *(float4*)(EX + (size_t)e * NH) = o;
    float* dn = denom + (size_t)t * NH;
    atomicAdd(dn + 0, o.x);
    atomicAdd(dn + 1, o.y);
    atomicAdd(dn + 2, o.z);
    atomicAdd(dn + 3, o.w);
}

// ---------------- edge pass 2 ----------------
__global__ __launch_bounds__(256) void edge2_kernel(const int* __restrict__ src,
                                                    const int* __restrict__ dst,
                                                    const float* __restrict__ EX,
                                                    const float* __restrict__ denom,
                                                    const float* __restrict__ T,
                                                    float* __restrict__ R) {
    int gwarp = (blockIdx.x * blockDim.x + threadIdx.x) >> 5;
    int lane = threadIdx.x & 31;
    if (gwarp >= NEDGES) return;
    int s = __ldg(src + gwarp);
    int t = __ldg(dst + gwarp);
    float4 ex = *(const float4*)(EX + (size_t)gwarp * NH);
    float4 dn = *(const float4*)(denom + (size_t)t * NH);
    float alpha[4] = { ex.x / dn.x, ex.y / dn.y, ex.z / dn.z, ex.w / dn.w };

    const float* Ts = T + (size_t)s * FDIM;
    float* Rt = R + (size_t)t * FDIM;
#pragma unroll
    for (int c = 0; c < 4; c++) {
        int off = c * HD + lane * 4;
        float4 hv = *(const float4*)(Ts + off);
        float a = alpha[c];
        atomicAdd(Rt + off + 0, a * hv.x);
        atomicAdd(Rt + off + 1, a * hv.y);
        atomicAdd(Rt + off + 2, a * hv.z);
        atomicAdd(Rt + off + 3, a * hv.w);
    }
}

// ---------------- final mean over heads ----------------
__global__ void mean_kernel(const float* __restrict__ R, float* __restrict__ out) {
    int i = blockIdx.x * blockDim.x + threadIdx.x;
    if (i >= NNODES * HD) return;
    int n = i >> 7;
    int d = i & 127;
    const float* r = R + (size_t)n * FDIM + d;
    float v = fmaxf(r[0], 0.f) + fmaxf(r[HD], 0.f) + fmaxf(r[2 * HD], 0.f) + fmaxf(r[3 * HD], 0.f);
    out[i] = 0.25f * v;
}

// ---------------- launch ----------------
extern "C" void kernel_launch(void* const* d_in, const int* in_sizes, int n_in,
                              void* d_out, int out_size) {
    const float* x   = (const float*)d_in[0];
    const int*   src = (const int*)d_in[1];
    const int*   dst = (const int*)d_in[2];
    const float* W0  = (const float*)d_in[3];
    const float* al0 = (const float*)d_in[4];
    const float* ar0 = (const float*)d_in[5];
    const float* W1  = (const float*)d_in[6];
    const float* al1 = (const float*)d_in[7];
    const float* ar1 = (const float*)d_in[8];
    float* out = (float*)d_out;

    float *T, *R, *EX, *el, *er, *denom;
    __nv_bfloat16 *Ahi, *Alo, *Whi, *Wlo;
    cudaGetSymbolAddress((void**)&T, g_T);
    cudaGetSymbolAddress((void**)&R, g_R);
    cudaGetSymbolAddress((void**)&EX, g_EX);
    cudaGetSymbolAddress((void**)&el, g_el);
    cudaGetSymbolAddress((void**)&er, g_er);
    cudaGetSymbolAddress((void**)&denom, g_denom);
    cudaGetSymbolAddress((void**)&Ahi, g_Ahi);
    cudaGetSymbolAddress((void**)&Alo, g_Alo);
    cudaGetSymbolAddress((void**)&Whi, g_Whi);
    cudaGetSymbolAddress((void**)&Wlo, g_Wlo);

    const size_t bigN4 = (size_t)NNODES * FDIM / 4;
    const size_t dnN4  = (size_t)NNODES * NH / 4;

    dim3 gemmGrid(FDIM / 128, (NNODES + 127) / 128);   // (4, 391)
    int elerBlocks  = (NNODES * NH + 7) / 8;
    int edge1Blocks = (NEDGES + 255) / 256;
    int edge2Blocks = (NEDGES + 7) / 8;
    int meanBlocks  = (NNODES * HD + 255) / 256;

    // ---------------- layer 0 ----------------
    zero_kernel<<<(unsigned)((bigN4 + 255) / 256), 256>>>(R, bigN4);
    zero_kernel<<<(unsigned)((dnN4 + 255) / 256), 256>>>(denom, dnN4);

    {
        size_t n4 = (size_t)NNODES * IN_DIM / 4;
        convA_kernel<<<(unsigned)((n4 + 255) / 256), 256>>>(x, Ahi, Alo, n4, 0);
        convW_kernel<<<(FDIM * IN_DIM + 255) / 256, 256>>>(W0, Whi, Wlo, IN_DIM);
        hmma_gemm<IN_DIM><<<gemmGrid, 256>>>(Ahi, Alo, Whi, Wlo, T, NNODES);
    }

    eler_kernel<<<elerBlocks, 256>>>(T, al0, ar0, el, er);
    edge1_kernel<<<edge1Blocks, 256>>>(src, dst, el, er, EX, denom);
    edge2_kernel<<<edge2Blocks, 256>>>(src, dst, EX, denom, T, R);

    // ---------------- layer 1 ----------------
    {
        size_t n4 = (size_t)NNODES * FDIM / 4;
        convA_kernel<<<(unsigned)((n4 + 255) / 256), 256>>>(R, Ahi, Alo, n4, 1);  // relu(R)
        convW_kernel<<<(FDIM * FDIM + 255) / 256, 256>>>(W1, Whi, Wlo, FDIM);
        hmma_gemm<FDIM><<<gemmGrid, 256>>>(Ahi, Alo, Whi, Wlo, T, NNODES);
    }

    zero_kernel<<<(unsigned)((bigN4 + 255) / 256), 256>>>(R, bigN4);
    zero_kernel<<<(unsigned)((dnN4 + 255) / 256), 256>>>(denom, dnN4);
    eler_kernel<<<elerBlocks, 256>>>(T, al1, ar1, el, er);
    edge1_kernel<<<edge1Blocks, 256>>>(src, dst, el, er, EX, denom);
    edge2_kernel<<<edge2Blocks, 256>>>(src, dst, EX, denom, T, R);

    mean_kernel<<<meanBlocks, 256>>>(R, out);
}

// round 5
// speedup vs baseline: 2.8637x; 2.3430x over previous
#include <cuda_runtime.h>
#include <cuda_bf16.h>
#include <cstdint>

// Problem constants
#define NNODES 50000
#define NEDGES 600000
#define IN_DIM 256
#define NH     4
#define HD     128
#define FDIM   (NH*HD)     // 512
#define NEG_SLOPE 0.2f

// ---------------- scratch (static __device__ — no allocations allowed) ----------------
__device__ float g_T[(size_t)NNODES * FDIM];     // h = x@W (per layer)
__device__ float g_el[NNODES * NH];
__device__ float g_er[NNODES * NH];
__device__ __nv_bfloat16 g_Ahi[(size_t)NNODES * FDIM];
__device__ __nv_bfloat16 g_Alo[(size_t)NNODES * FDIM];
__device__ __nv_bfloat16 g_Whi[(size_t)FDIM * FDIM];   // W^T [N, K] bf16 hi
__device__ __nv_bfloat16 g_Wlo[(size_t)FDIM * FDIM];   // W^T [N, K] bf16 lo
// CSR scratch
__device__ int g_deg[NNODES];
__device__ int g_rowptr[NNODES + 1];
__device__ int g_cursor[NNODES];
__device__ int g_csrc[NEDGES];

// ---------------- small utils ----------------
__global__ void zero_int_kernel(int* p, int n) {
    int i = blockIdx.x * blockDim.x + threadIdx.x;
    if (i < n) p[i] = 0;
}

__global__ void hist_kernel(const int* __restrict__ dst, int* __restrict__ deg) {
    int e = blockIdx.x * blockDim.x + threadIdx.x;
    if (e < NEDGES) atomicAdd(&deg[dst[e]], 1);
}

// single-block Hillis-Steele scan over NNODES, emits rowptr (exclusive) + cursor copy
__global__ __launch_bounds__(1024) void scan_kernel(const int* __restrict__ deg,
                                                    int* __restrict__ rowptr,
                                                    int* __restrict__ cursor) {
    __shared__ int sA[1024], sB[1024];
    int tid = threadIdx.x;
    int carry = 0;
    for (int base = 0; base < NNODES; base += 1024) {
        int i = base + tid;
        int v = (i < NNODES) ? deg[i] : 0;
        sA[tid] = v;
        __syncthreads();
        int* in = sA; int* out = sB;
#pragma unroll
        for (int off = 1; off < 1024; off <<= 1) {
            int x = in[tid];
            if (tid >= off) x += in[tid - off];
            out[tid] = x;
            __syncthreads();
            int* t = in; in = out; out = t;
        }
        int incl = in[tid];
        int excl = incl - v;
        if (i < NNODES) { rowptr[i] = carry + excl; cursor[i] = carry + excl; }
        int total = in[1023];
        __syncthreads();
        carry += total;
    }
    if (tid == 0) rowptr[NNODES] = carry;
}

__global__ void scatter_kernel(const int* __restrict__ src, const int* __restrict__ dst,
                               int* __restrict__ cursor, int* __restrict__ csrc) {
    int e = blockIdx.x * blockDim.x + threadIdx.x;
    if (e >= NEDGES) return;
    int pos = atomicAdd(&cursor[dst[e]], 1);
    csrc[pos] = src[e];
}

// ---------------- fp32 -> bf16 hi/lo split (element-wise) ----------------
__global__ void convA_kernel(const float* __restrict__ in,
                             __nv_bfloat16* __restrict__ hi,
                             __nv_bfloat16* __restrict__ lo, size_t n4) {
    size_t i = (size_t)blockIdx.x * blockDim.x + threadIdx.x;
    if (i >= n4) return;
    float4 v = ((const float4*)in)[i];
    __nv_bfloat16 h0 = __float2bfloat16_rn(v.x), h1 = __float2bfloat16_rn(v.y);
    __nv_bfloat16 h2 = __float2bfloat16_rn(v.z), h3 = __float2bfloat16_rn(v.w);
    __nv_bfloat16 l0 = __float2bfloat16_rn(v.x - __bfloat162float(h0));
    __nv_bfloat16 l1 = __float2bfloat16_rn(v.y - __bfloat162float(h1));
    __nv_bfloat16 l2 = __float2bfloat16_rn(v.z - __bfloat162float(h2));
    __nv_bfloat16 l3 = __float2bfloat16_rn(v.w - __bfloat162float(h3));
    ((__nv_bfloat162*)hi)[i * 2 + 0] = __nv_bfloat162(h0, h1);
    ((__nv_bfloat162*)hi)[i * 2 + 1] = __nv_bfloat162(h2, h3);
    ((__nv_bfloat162*)lo)[i * 2 + 0] = __nv_bfloat162(l0, l1);
    ((__nv_bfloat162*)lo)[i * 2 + 1] = __nv_bfloat162(l2, l3);
}

// ---------------- W[K,512] -> W^T[512,K] bf16 hi/lo ----------------
__global__ void convW_kernel(const float* __restrict__ W,
                             __nv_bfloat16* __restrict__ hi,
                             __nv_bfloat16* __restrict__ lo, int K) {
    int idx = blockIdx.x * blockDim.x + threadIdx.x;
    if (idx >= FDIM * K) return;
    int n = idx / K, k = idx - n * K;
    float v = W[(size_t)k * FDIM + n];
    __nv_bfloat16 h = __float2bfloat16_rn(v);
    hi[idx] = h;
    lo[idx] = __float2bfloat16_rn(v - __bfloat162float(h));
}

// ---------------- HMMA GEMM (unchanged from R4): C[M,512] = A @ B^T, 3-term bf16 ----------------
#define MMA_BF16(d, a, b)                                                            \
    asm volatile("mma.sync.aligned.m16n8k16.row.col.f32.bf16.bf16.f32 "              \
        "{%0,%1,%2,%3}, {%4,%5,%6,%7}, {%8,%9}, {%0,%1,%2,%3};"                      \
        : "+f"((d)[0]), "+f"((d)[1]), "+f"((d)[2]), "+f"((d)[3])                     \
        : "r"((a)[0]), "r"((a)[1]), "r"((a)[2]), "r"((a)[3]),                        \
          "r"((b)[0]), "r"((b)[1]))

template <int K>
__global__ __launch_bounds__(256) void hmma_gemm(const __nv_bfloat16* __restrict__ Ahi,
                                                 const __nv_bfloat16* __restrict__ Alo,
                                                 const __nv_bfloat16* __restrict__ Bhi,
                                                 const __nv_bfloat16* __restrict__ Blo,
                                                 float* __restrict__ C, int M) {
    __shared__ __nv_bfloat16 sAh[128][40];
    __shared__ __nv_bfloat16 sAl[128][40];
    __shared__ __nv_bfloat16 sBh[128][40];
    __shared__ __nv_bfloat16 sBl[128][40];

    int tid = threadIdx.x;
    int lane = tid & 31;
    int wid = tid >> 5;
    int wr = wid & 3;
    int wc = wid >> 2;
    int gr4 = lane >> 2;
    int tig = lane & 3;

    int row0 = blockIdx.y * 128;
    int col0 = blockIdx.x * 128;

    float acc[2][8][4];
#pragma unroll
    for (int mt = 0; mt < 2; mt++)
#pragma unroll
        for (int nt = 0; nt < 8; nt++)
#pragma unroll
            for (int q = 0; q < 4; q++) acc[mt][nt][q] = 0.f;

#pragma unroll 1
    for (int kt = 0; kt < K / 32; kt++) {
        int k0 = kt * 32;
        __syncthreads();
#pragma unroll
        for (int j = 0; j < 2; j++) {
            int idx = tid + j * 256;
            int r = idx >> 2, c = (idx & 3) * 8;
            int gr = row0 + r;
            uint4 vh = make_uint4(0u, 0u, 0u, 0u), vl = vh;
            if (gr < M) {
                vh = *(const uint4*)(Ahi + (size_t)gr * K + k0 + c);
                vl = *(const uint4*)(Alo + (size_t)gr * K + k0 + c);
            }
            *(uint4*)&sAh[r][c] = vh;
            *(uint4*)&sAl[r][c] = vl;
            *(uint4*)&sBh[r][c] = *(const uint4*)(Bhi + (size_t)(col0 + r) * K + k0 + c);
            *(uint4*)&sBl[r][c] = *(const uint4*)(Blo + (size_t)(col0 + r) * K + k0 + c);
        }
        __syncthreads();

#pragma unroll
        for (int ks = 0; ks < 2; ks++) {
            int kb = ks * 16;
            uint32_t ah[2][4], al[2][4];
#pragma unroll
            for (int mt = 0; mt < 2; mt++) {
                int mr = wr * 32 + mt * 16 + gr4;
                ah[mt][0] = *(const uint32_t*)&sAh[mr][kb + tig * 2];
                ah[mt][1] = *(const uint32_t*)&sAh[mr + 8][kb + tig * 2];
                ah[mt][2] = *(const uint32_t*)&sAh[mr][kb + 8 + tig * 2];
                ah[mt][3] = *(const uint32_t*)&sAh[mr + 8][kb + 8 + tig * 2];
                al[mt][0] = *(const uint32_t*)&sAl[mr][kb + tig * 2];
                al[mt][1] = *(const uint32_t*)&sAl[mr + 8][kb + tig * 2];
                al[mt][2] = *(const uint32_t*)&sAl[mr][kb + 8 + tig * 2];
                al[mt][3] = *(const uint32_t*)&sAl[mr + 8][kb + 8 + tig * 2];
            }
#pragma unroll
            for (int nt = 0; nt < 8; nt++) {
                int nc = wc * 64 + nt * 8 + gr4;
                uint32_t bh[2], bl[2];
                bh[0] = *(const uint32_t*)&sBh[nc][kb + tig * 2];
                bh[1] = *(const uint32_t*)&sBh[nc][kb + 8 + tig * 2];
                bl[0] = *(const uint32_t*)&sBl[nc][kb + tig * 2];
                bl[1] = *(const uint32_t*)&sBl[nc][kb + 8 + tig * 2];
#pragma unroll
                for (int mt = 0; mt < 2; mt++) {
                    MMA_BF16(acc[mt][nt], ah[mt], bh);
                    MMA_BF16(acc[mt][nt], ah[mt], bl);
                    MMA_BF16(acc[mt][nt], al[mt], bh);
                }
            }
        }
    }

#pragma unroll
    for (int mt = 0; mt < 2; mt++) {
        int r0 = row0 + wr * 32 + mt * 16 + gr4;
#pragma unroll
        for (int nt = 0; nt < 8; nt++) {
            int cc = col0 + wc * 64 + nt * 8 + tig * 2;
            if (r0 < M)
                *(float2*)(C + (size_t)r0 * FDIM + cc) = make_float2(acc[mt][nt][0], acc[mt][nt][1]);
            if (r0 + 8 < M)
                *(float2*)(C + (size_t)(r0 + 8) * FDIM + cc) = make_float2(acc[mt][nt][2], acc[mt][nt][3]);
        }
    }
}

// ---------------- el/er: per (node, head) dot products ----------------
__global__ void eler_kernel(const float* __restrict__ T,
                            const float* __restrict__ al,
                            const float* __restrict__ ar,
                            float* __restrict__ el, float* __restrict__ er) {
    int warp = (blockIdx.x * blockDim.x + threadIdx.x) >> 5;
    int lane = threadIdx.x & 31;
    if (warp >= NNODES * NH) return;
    int n = warp >> 2;
    int h = warp & 3;

    const float4 tv = *(const float4*)(T + (size_t)n * FDIM + h * HD + lane * 4);
    const float4 av = *(const float4*)(al + h * HD + lane * 4);
    const float4 rv = *(const float4*)(ar + h * HD + lane * 4);

    float sl = tv.x * av.x + tv.y * av.y + tv.z * av.z + tv.w * av.w;
    float sr = tv.x * rv.x + tv.y * rv.y + tv.z * rv.z + tv.w * rv.w;
#pragma unroll
    for (int o = 16; o > 0; o >>= 1) {
        sl += __shfl_xor_sync(0xFFFFFFFFu, sl, o);
        sr += __shfl_xor_sync(0xFFFFFFFFu, sr, o);
    }
    if (lane == 0) { el[warp] = sl; er[warp] = sr; }
}

__device__ __forceinline__ float lrelu_exp(float v) {
    v = v > 0.f ? v : NEG_SLOPE * v;
    return __expf(v);
}

// ---------------- CSR aggregation: one warp per dst node ----------------
// MODE 0: write relu(rst) as bf16 hi/lo (feeds layer-1 GEMM directly)
// MODE 1: write out[n,128] = mean over heads of relu(rst)
template <int MODE>
__global__ __launch_bounds__(256) void agg_kernel(const int* __restrict__ rowptr,
                                                  const int* __restrict__ csrc,
                                                  const float* __restrict__ el,
                                                  const float* __restrict__ er,
                                                  const float* __restrict__ T,
                                                  __nv_bfloat16* __restrict__ Ahi,
                                                  __nv_bfloat16* __restrict__ Alo,
                                                  float* __restrict__ out) {
    int t = (blockIdx.x * blockDim.x + threadIdx.x) >> 5;
    int lane = threadIdx.x & 31;
    if (t >= NNODES) return;
    int rs = rowptr[t], re = rowptr[t + 1];

    float4 er4 = *(const float4*)(er + (size_t)t * NH);

    // phase 1: denom per head
    float d0 = 0.f, d1 = 0.f, d2 = 0.f, d3 = 0.f;
    for (int i = rs + lane; i < re; i += 32) {
        int s = __ldg(csrc + i);
        float4 l4 = *(const float4*)(el + (size_t)s * NH);
        d0 += lrelu_exp(l4.x + er4.x);
        d1 += lrelu_exp(l4.y + er4.y);
        d2 += lrelu_exp(l4.z + er4.z);
        d3 += lrelu_exp(l4.w + er4.w);
    }
#pragma unroll
    for (int o = 16; o > 0; o >>= 1) {
        d0 += __shfl_xor_sync(0xFFFFFFFFu, d0, o);
        d1 += __shfl_xor_sync(0xFFFFFFFFu, d1, o);
        d2 += __shfl_xor_sync(0xFFFFFFFFu, d2, o);
        d3 += __shfl_xor_sync(0xFFFFFFFFu, d3, o);
    }
    int head = lane >> 3;            // 8 lanes per head
    float dn = (head == 0) ? d0 : (head == 1) ? d1 : (head == 2) ? d2 : d3;
    float inv_dn = (dn > 0.f) ? (1.f / dn) : 0.f;
    float er_own = (head == 0) ? er4.x : (head == 1) ? er4.y : (head == 2) ? er4.z : er4.w;

    // phase 2: accumulate alpha * h[src]; lane owns features [lane*16, lane*16+16)
    float acc[16];
#pragma unroll
    for (int j = 0; j < 16; j++) acc[j] = 0.f;

    for (int i0 = rs; i0 < re; i0 += 32) {
        int s_l = (i0 + lane < re) ? __ldg(csrc + i0 + lane) : 0;
        int cnt = min(32, re - i0);
        for (int j = 0; j < cnt; j++) {
            int s = __shfl_sync(0xFFFFFFFFu, s_l, j);
            float a = lrelu_exp(__ldg(el + (size_t)s * NH + head) + er_own) * inv_dn;
            const float4* hp = (const float4*)(T + (size_t)s * FDIM + lane * 16);
            float4 v0 = hp[0], v1 = hp[1], v2 = hp[2], v3 = hp[3];
            acc[0]  += a * v0.x; acc[1]  += a * v0.y; acc[2]  += a * v0.z; acc[3]  += a * v0.w;
            acc[4]  += a * v1.x; acc[5]  += a * v1.y; acc[6]  += a * v1.z; acc[7]  += a * v1.w;
            acc[8]  += a * v2.x; acc[9]  += a * v2.y; acc[10] += a * v2.z; acc[11] += a * v2.w;
            acc[12] += a * v3.x; acc[13] += a * v3.y; acc[14] += a * v3.z; acc[15] += a * v3.w;
        }
    }

    if (MODE == 0) {
        // relu + bf16 hi/lo split, packed stores (16 bf16 = 2 uint4 each)
        uint32_t ph[8], pl[8];
#pragma unroll
        for (int j = 0; j < 8; j++) {
            float va = fmaxf(acc[j * 2 + 0], 0.f);
            float vb = fmaxf(acc[j * 2 + 1], 0.f);
            __nv_bfloat16 ha = __float2bfloat16_rn(va);
            __nv_bfloat16 hb = __float2bfloat16_rn(vb);
            __nv_bfloat16 la = __float2bfloat16_rn(va - __bfloat162float(ha));
            __nv_bfloat16 lb = __float2bfloat16_rn(vb - __bfloat162float(hb));
            __nv_bfloat162 hh(ha, hb), ll(la, lb);
            ph[j] = *(uint32_t*)&hh;
            pl[j] = *(uint32_t*)&ll;
        }
        size_t off = (size_t)t * FDIM + lane * 16;
        *(uint4*)(Ahi + off)     = make_uint4(ph[0], ph[1], ph[2], ph[3]);
        *(uint4*)(Ahi + off + 8) = make_uint4(ph[4], ph[5], ph[6], ph[7]);
        *(uint4*)(Alo + off)     = make_uint4(pl[0], pl[1], pl[2], pl[3]);
        *(uint4*)(Alo + off + 8) = make_uint4(pl[4], pl[5], pl[6], pl[7]);
    } else {
        // relu, then mean over heads: lanes {l, l^8, l^16, l^24} share features
        float r[16];
#pragma unroll
        for (int j = 0; j < 16; j++) {
            r[j] = fmaxf(acc[j], 0.f);
            r[j] += __shfl_xor_sync(0xFFFFFFFFu, r[j], 8);
            r[j] += __shfl_xor_sync(0xFFFFFFFFu, r[j], 16);
        }
        if (lane < 8) {
            float* op = out + (size_t)t * HD + lane * 16;
#pragma unroll
            for (int j = 0; j < 4; j++)
                *(float4*)(op + j * 4) = make_float4(0.25f * r[j * 4 + 0], 0.25f * r[j * 4 + 1],
                                                     0.25f * r[j * 4 + 2], 0.25f * r[j * 4 + 3]);
        }
    }
}

// ---------------- launch ----------------
extern "C" void kernel_launch(void* const* d_in, const int* in_sizes, int n_in,
                              void* d_out, int out_size) {
    const float* x   = (const float*)d_in[0];
    const int*   src = (const int*)d_in[1];
    const int*   dst = (const int*)d_in[2];
    const float* W0  = (const float*)d_in[3];
    const float* al0 = (const float*)d_in[4];
    const float* ar0 = (const float*)d_in[5];
    const float* W1  = (const float*)d_in[6];
    const float* al1 = (const float*)d_in[7];
    const float* ar1 = (const float*)d_in[8];
    float* out = (float*)d_out;

    float *T, *el, *er;
    __nv_bfloat16 *Ahi, *Alo, *Whi, *Wlo;
    int *deg, *rowptr, *cursor, *csrc;
    cudaGetSymbolAddress((void**)&T, g_T);
    cudaGetSymbolAddress((void**)&el, g_el);
    cudaGetSymbolAddress((void**)&er, g_er);
    cudaGetSymbolAddress((void**)&Ahi, g_Ahi);
    cudaGetSymbolAddress((void**)&Alo, g_Alo);
    cudaGetSymbolAddress((void**)&Whi, g_Whi);
    cudaGetSymbolAddress((void**)&Wlo, g_Wlo);
    cudaGetSymbolAddress((void**)&deg, g_deg);
    cudaGetSymbolAddress((void**)&rowptr, g_rowptr);
    cudaGetSymbolAddress((void**)&cursor, g_cursor);
    cudaGetSymbolAddress((void**)&csrc, g_csrc);

    dim3 gemmGrid(FDIM / 128, (NNODES + 127) / 128);   // (4, 391)
    int elerBlocks = (NNODES * NH + 7) / 8;
    int aggBlocks  = (NNODES + 7) / 8;                  // 8 warps/block
    int edgeBlocks = (NEDGES + 255) / 256;

    // ---------------- CSR build (reused by both layers) ----------------
    zero_int_kernel<<<(NNODES + 255) / 256, 256>>>(deg, NNODES);
    hist_kernel<<<edgeBlocks, 256>>>(dst, deg);
    scan_kernel<<<1, 1024>>>(deg, rowptr, cursor);
    scatter_kernel<<<edgeBlocks, 256>>>(src, dst, cursor, csrc);

    // ---------------- layer 0 ----------------
    {
        size_t n4 = (size_t)NNODES * IN_DIM / 4;
        convA_kernel<<<(unsigned)((n4 + 255) / 256), 256>>>(x, Ahi, Alo, n4);
        convW_kernel<<<(FDIM * IN_DIM + 255) / 256, 256>>>(W0, Whi, Wlo, IN_DIM);
        hmma_gemm<IN_DIM><<<gemmGrid, 256>>>(Ahi, Alo, Whi, Wlo, T, NNODES);
    }
    eler_kernel<<<elerBlocks, 256>>>(T, al0, ar0, el, er);
    agg_kernel<0><<<aggBlocks, 256>>>(rowptr, csrc, el, er, T, Ahi, Alo, nullptr);

    // ---------------- layer 1 ----------------
    {
        convW_kernel<<<(FDIM * FDIM + 255) / 256, 256>>>(W1, Whi, Wlo, FDIM);
        hmma_gemm<FDIM><<<gemmGrid, 256>>>(Ahi, Alo, Whi, Wlo, T, NNODES);
    }
    eler_kernel<<<elerBlocks, 256>>>(T, al1, ar1, el, er);
    agg_kernel<1><<<aggBlocks, 256>>>(rowptr, csrc, el, er, T, nullptr, nullptr, out);
}

// round 6
// speedup vs baseline: 3.2126x; 1.1218x over previous
#include <cuda_runtime.h>
#include <cuda_bf16.h>
#include <cstdint>

// Problem constants
#define NNODES 50000
#define NEDGES 600000
#define IN_DIM 256
#define NH     4
#define HD     128
#define FDIM   (NH*HD)     // 512
#define NEG_SLOPE 0.2f

// ---------------- scratch (static __device__ — no allocations allowed) ----------------
__device__ float g_T[(size_t)NNODES * FDIM];     // h = x@W (per layer)
__device__ float g_el[NNODES * NH];
__device__ float g_er[NNODES * NH];
__device__ float g_EX[(size_t)NEDGES * NH];      // exp(e) per CSR edge slot
__device__ __nv_bfloat16 g_Ahi[(size_t)NNODES * FDIM];
__device__ __nv_bfloat16 g_Alo[(size_t)NNODES * FDIM];
__device__ __nv_bfloat16 g_Whi[(size_t)FDIM * FDIM];   // W^T [N, K] bf16 hi
__device__ __nv_bfloat16 g_Wlo[(size_t)FDIM * FDIM];   // W^T [N, K] bf16 lo
// CSR scratch
__device__ int g_deg[NNODES];
__device__ int g_rowptr[NNODES + 1];
__device__ int g_cursor[NNODES];
__device__ int g_csrc[NEDGES];

// ---------------- small utils ----------------
__global__ void zero_int_kernel(int* p, int n) {
    int i = blockIdx.x * blockDim.x + threadIdx.x;
    if (i < n) p[i] = 0;
}

__global__ void hist_kernel(const int* __restrict__ dst, int* __restrict__ deg) {
    int e = blockIdx.x * blockDim.x + threadIdx.x;
    if (e < NEDGES) atomicAdd(&deg[dst[e]], 1);
}

// single-block Hillis-Steele scan over NNODES, emits rowptr (exclusive) + cursor copy
__global__ __launch_bounds__(1024) void scan_kernel(const int* __restrict__ deg,
                                                    int* __restrict__ rowptr,
                                                    int* __restrict__ cursor) {
    __shared__ int sA[1024], sB[1024];
    int tid = threadIdx.x;
    int carry = 0;
    for (int base = 0; base < NNODES; base += 1024) {
        int i = base + tid;
        int v = (i < NNODES) ? deg[i] : 0;
        sA[tid] = v;
        __syncthreads();
        int* in = sA; int* out = sB;
#pragma unroll
        for (int off = 1; off < 1024; off <<= 1) {
            int x = in[tid];
            if (tid >= off) x += in[tid - off];
            out[tid] = x;
            __syncthreads();
            int* t = in; in = out; out = t;
        }
        int incl = in[tid];
        int excl = incl - v;
        if (i < NNODES) { rowptr[i] = carry + excl; cursor[i] = carry + excl; }
        int total = in[1023];
        __syncthreads();
        carry += total;
    }
    if (tid == 0) rowptr[NNODES] = carry;
}

__global__ void scatter_kernel(const int* __restrict__ src, const int* __restrict__ dst,
                               int* __restrict__ cursor, int* __restrict__ csrc) {
    int e = blockIdx.x * blockDim.x + threadIdx.x;
    if (e >= NEDGES) return;
    int pos = atomicAdd(&cursor[dst[e]], 1);
    csrc[pos] = src[e];
}

// ---------------- fp32 -> bf16 hi/lo split (element-wise) ----------------
__global__ void convA_kernel(const float* __restrict__ in,
                             __nv_bfloat16* __restrict__ hi,
                             __nv_bfloat16* __restrict__ lo, size_t n4) {
    size_t i = (size_t)blockIdx.x * blockDim.x + threadIdx.x;
    if (i >= n4) return;
    float4 v = ((const float4*)in)[i];
    __nv_bfloat16 h0 = __float2bfloat16_rn(v.x), h1 = __float2bfloat16_rn(v.y);
    __nv_bfloat16 h2 = __float2bfloat16_rn(v.z), h3 = __float2bfloat16_rn(v.w);
    __nv_bfloat16 l0 = __float2bfloat16_rn(v.x - __bfloat162float(h0));
    __nv_bfloat16 l1 = __float2bfloat16_rn(v.y - __bfloat162float(h1));
    __nv_bfloat16 l2 = __float2bfloat16_rn(v.z - __bfloat162float(h2));
    __nv_bfloat16 l3 = __float2bfloat16_rn(v.w - __bfloat162float(h3));
    ((__nv_bfloat162*)hi)[i * 2 + 0] = __nv_bfloat162(h0, h1);
    ((__nv_bfloat162*)hi)[i * 2 + 1] = __nv_bfloat162(h2, h3);
    ((__nv_bfloat162*)lo)[i * 2 + 0] = __nv_bfloat162(l0, l1);
    ((__nv_bfloat162*)lo)[i * 2 + 1] = __nv_bfloat162(l2, l3);
}

// ---------------- W[K,512] -> W^T[512,K] bf16 hi/lo ----------------
__global__ void convW_kernel(const float* __restrict__ W,
                             __nv_bfloat16* __restrict__ hi,
                             __nv_bfloat16* __restrict__ lo, int K) {
    int idx = blockIdx.x * blockDim.x + threadIdx.x;
    if (idx >= FDIM * K) return;
    int n = idx / K, k = idx - n * K;
    float v = W[(size_t)k * FDIM + n];
    __nv_bfloat16 h = __float2bfloat16_rn(v);
    hi[idx] = h;
    lo[idx] = __float2bfloat16_rn(v - __bfloat162float(h));
}

// ---------------- HMMA GEMM with cp.async 2-stage pipeline ----------------
// C[M,512] = A[M,K] @ B^T, 3-term bf16 hi/lo split.
// CTA tile 128x128, BK=32, 8 warps (32x64 warp tile). Dynamic smem: 2 stages x 40960 B.
#define MMA_BF16(d, a, b)                                                            \
    asm volatile("mma.sync.aligned.m16n8k16.row.col.f32.bf16.bf16.f32 "              \
        "{%0,%1,%2,%3}, {%4,%5,%6,%7}, {%8,%9}, {%0,%1,%2,%3};"                      \
        : "+f"((d)[0]), "+f"((d)[1]), "+f"((d)[2]), "+f"((d)[3])                     \
        : "r"((a)[0]), "r"((a)[1]), "r"((a)[2]), "r"((a)[3]),                        \
          "r"((b)[0]), "r"((b)[1]))

__device__ __forceinline__ void cp16(uint32_t d, const void* g, int sz) {
    asm volatile("cp.async.cg.shared.global [%0], [%1], 16, %2;" :: "r"(d), "l"(g), "r"(sz));
}
__device__ __forceinline__ void cp_commit() { asm volatile("cp.async.commit_group;" ::: "memory"); }
template <int N>
__device__ __forceinline__ void cp_wait() { asm volatile("cp.async.wait_group %0;" :: "n"(N) : "memory"); }

static constexpr int GS_BUF   = 10240;   // 128 rows * 40 elems * 2B
static constexpr int GS_STAGE = 4 * GS_BUF;  // Ah, Al, Bh, Bl
static constexpr int GS_TOTAL = 2 * GS_STAGE;  // 81920

template <int K>
__global__ __launch_bounds__(256) void hmma_gemm(const __nv_bfloat16* __restrict__ Ahi,
                                                 const __nv_bfloat16* __restrict__ Alo,
                                                 const __nv_bfloat16* __restrict__ Bhi,
                                                 const __nv_bfloat16* __restrict__ Blo,
                                                 float* __restrict__ C, int M) {
    extern __shared__ char smem[];
    uint32_t sbase;
    asm("{ .reg .u64 t; cvta.to.shared.u64 t, %1; cvt.u32.u64 %0, t; }" : "=r"(sbase) : "l"(smem));

    int tid = threadIdx.x;
    int lane = tid & 31;
    int wid = tid >> 5;
    int wr = wid & 3;
    int wc = wid >> 2;
    int gr4 = lane >> 2;
    int tig = lane & 3;

    int row0 = blockIdx.y * 128;
    int col0 = blockIdx.x * 128;

    const __nv_bfloat16* gsrc[4] = { Ahi, Alo, Bhi, Blo };

    // stage loader: 2048 16B chunks, 8 per thread; buf = j>>1 (compile-time per j)
    auto load_stage = [&](int kt, int st) {
        int k0 = kt * 32;
#pragma unroll
        for (int j = 0; j < 8; j++) {
            const int buf = j >> 1;
            int rem = (j & 1) * 256 + tid;      // 0..511
            int r = rem >> 2, c = (rem & 3) * 8;
            uint32_t doff = sbase + st * GS_STAGE + buf * GS_BUF + (r * 40 + c) * 2;
            int gr = (buf < 2) ? (row0 + r) : (col0 + r);
            const void* gp = gsrc[buf] + (size_t)gr * K + k0 + c;
            int sz = (buf < 2 && gr >= M) ? 0 : 16;
            cp16(doff, gp, sz);
        }
    };

    float acc[2][8][4];
#pragma unroll
    for (int mt = 0; mt < 2; mt++)
#pragma unroll
        for (int nt = 0; nt < 8; nt++)
#pragma unroll
            for (int q = 0; q < 4; q++) acc[mt][nt][q] = 0.f;

    const int NK = K / 32;
    load_stage(0, 0);
    cp_commit();

#pragma unroll 1
    for (int kt = 0; kt < NK; kt++) {
        int st = kt & 1;
        if (kt + 1 < NK) { load_stage(kt + 1, st ^ 1); cp_commit(); cp_wait<1>(); }
        else            { cp_wait<0>(); }
        __syncthreads();

        const __nv_bfloat16* pAh = (const __nv_bfloat16*)(smem + st * GS_STAGE);
        const __nv_bfloat16* pAl = (const __nv_bfloat16*)(smem + st * GS_STAGE + GS_BUF);
        const __nv_bfloat16* pBh = (const __nv_bfloat16*)(smem + st * GS_STAGE + 2 * GS_BUF);
        const __nv_bfloat16* pBl = (const __nv_bfloat16*)(smem + st * GS_STAGE + 3 * GS_BUF);

#pragma unroll
        for (int ks = 0; ks < 2; ks++) {
            int kb = ks * 16;
            uint32_t ah[2][4], al[2][4];
#pragma unroll
            for (int mt = 0; mt < 2; mt++) {
                int mr = wr * 32 + mt * 16 + gr4;
                ah[mt][0] = *(const uint32_t*)(pAh + mr * 40 + kb + tig * 2);
                ah[mt][1] = *(const uint32_t*)(pAh + (mr + 8) * 40 + kb + tig * 2);
                ah[mt][2] = *(const uint32_t*)(pAh + mr * 40 + kb + 8 + tig * 2);
                ah[mt][3] = *(const uint32_t*)(pAh + (mr + 8) * 40 + kb + 8 + tig * 2);
                al[mt][0] = *(const uint32_t*)(pAl + mr * 40 + kb + tig * 2);
                al[mt][1] = *(const uint32_t*)(pAl + (mr + 8) * 40 + kb + tig * 2);
                al[mt][2] = *(const uint32_t*)(pAl + mr * 40 + kb + 8 + tig * 2);
                al[mt][3] = *(const uint32_t*)(pAl + (mr + 8) * 40 + kb + 8 + tig * 2);
            }
#pragma unroll
            for (int nt = 0; nt < 8; nt++) {
                int nc = wc * 64 + nt * 8 + gr4;
                uint32_t bh[2], bl[2];
                bh[0] = *(const uint32_t*)(pBh + nc * 40 + kb + tig * 2);
                bh[1] = *(const uint32_t*)(pBh + nc * 40 + kb + 8 + tig * 2);
                bl[0] = *(const uint32_t*)(pBl + nc * 40 + kb + tig * 2);
                bl[1] = *(const uint32_t*)(pBl + nc * 40 + kb + 8 + tig * 2);
#pragma unroll
                for (int mt = 0; mt < 2; mt++) {
                    MMA_BF16(acc[mt][nt], ah[mt], bh);
                    MMA_BF16(acc[mt][nt], ah[mt], bl);
                    MMA_BF16(acc[mt][nt], al[mt], bh);
                }
            }
        }
        __syncthreads();   // protect stage buffer from next prefetch
    }

#pragma unroll
    for (int mt = 0; mt < 2; mt++) {
        int r0 = row0 + wr * 32 + mt * 16 + gr4;
#pragma unroll
        for (int nt = 0; nt < 8; nt++) {
            int cc = col0 + wc * 64 + nt * 8 + tig * 2;
            if (r0 < M)
                *(float2*)(C + (size_t)r0 * FDIM + cc) = make_float2(acc[mt][nt][0], acc[mt][nt][1]);
            if (r0 + 8 < M)
                *(float2*)(C + (size_t)(r0 + 8) * FDIM + cc) = make_float2(acc[mt][nt][2], acc[mt][nt][3]);
        }
    }
}

// ---------------- el/er: per (node, head) dot products ----------------
__global__ void eler_kernel(const float* __restrict__ T,
                            const float* __restrict__ al,
                            const float* __restrict__ ar,
                            float* __restrict__ el, float* __restrict__ er) {
    int warp = (blockIdx.x * blockDim.x + threadIdx.x) >> 5;
    int lane = threadIdx.x & 31;
    if (warp >= NNODES * NH) return;
    int n = warp >> 2;
    int h = warp & 3;

    const float4 tv = *(const float4*)(T + (size_t)n * FDIM + h * HD + lane * 4);
    const float4 av = *(const float4*)(al + h * HD + lane * 4);
    const float4 rv = *(const float4*)(ar + h * HD + lane * 4);

    float sl = tv.x * av.x + tv.y * av.y + tv.z * av.z + tv.w * av.w;
    float sr = tv.x * rv.x + tv.y * rv.y + tv.z * rv.z + tv.w * rv.w;
#pragma unroll
    for (int o = 16; o > 0; o >>= 1) {
        sl += __shfl_xor_sync(0xFFFFFFFFu, sl, o);
        sr += __shfl_xor_sync(0xFFFFFFFFu, sr, o);
    }
    if (lane == 0) { el[warp] = sl; er[warp] = sr; }
}

__device__ __forceinline__ float lrelu_exp(float v) {
    v = v > 0.f ? v : NEG_SLOPE * v;
    return __expf(v);
}

// ---------------- CSR aggregation: one warp per dst node ----------------
// Phase 1 computes exp(e) per edge (stored to EX at CSR slot) + denom.
// Phase 2 reads alpha from EX — no dependent el gather / exp recompute.
// MODE 0: write relu(rst) as bf16 hi/lo; MODE 1: write head-mean to out.
template <int MODE>
__global__ __launch_bounds__(256) void agg_kernel(const int* __restrict__ rowptr,
                                                  const int* __restrict__ csrc,
                                                  const float* __restrict__ el,
                                                  const float* __restrict__ er,
                                                  const float* __restrict__ T,
                                                  float* __restrict__ EX,
                                                  __nv_bfloat16* __restrict__ Ahi,
                                                  __nv_bfloat16* __restrict__ Alo,
                                                  float* __restrict__ out) {
    int t = (blockIdx.x * blockDim.x + threadIdx.x) >> 5;
    int lane = threadIdx.x & 31;
    if (t >= NNODES) return;
    int rs = rowptr[t], re = rowptr[t + 1];

    float4 er4 = *(const float4*)(er + (size_t)t * NH);

    // phase 1: exp per edge -> EX, accumulate denom per head
    float d0 = 0.f, d1 = 0.f, d2 = 0.f, d3 = 0.f;
    for (int i = rs + lane; i < re; i += 32) {
        int s = __ldg(csrc + i);
        float4 l4 = *(const float4*)(el + (size_t)s * NH);
        float4 ex;
        ex.x = lrelu_exp(l4.x + er4.x);
        ex.y = lrelu_exp(l4.y + er4.y);
        ex.z = lrelu_exp(l4.z + er4.z);
        ex.w = lrelu_exp(l4.w + er4.w);
        *(float4*)(EX + (size_t)i * NH) = ex;
        d0 += ex.x; d1 += ex.y; d2 += ex.z; d3 += ex.w;
    }
#pragma unroll
    for (int o = 16; o > 0; o >>= 1) {
        d0 += __shfl_xor_sync(0xFFFFFFFFu, d0, o);
        d1 += __shfl_xor_sync(0xFFFFFFFFu, d1, o);
        d2 += __shfl_xor_sync(0xFFFFFFFFu, d2, o);
        d3 += __shfl_xor_sync(0xFFFFFFFFu, d3, o);
    }
    __syncwarp();   // EX stores visible to whole warp

    int head = lane >> 3;            // 8 lanes per head
    float dn = (head == 0) ? d0 : (head == 1) ? d1 : (head == 2) ? d2 : d3;
    float inv_dn = (dn > 0.f) ? (1.f / dn) : 0.f;

    // phase 2: accumulate alpha * h[src]; lane owns features [lane*16, lane*16+16)
    float acc[16];
#pragma unroll
    for (int j = 0; j < 16; j++) acc[j] = 0.f;

    for (int i0 = rs; i0 < re; i0 += 32) {
        int s_l = (i0 + lane < re) ? __ldg(csrc + i0 + lane) : 0;
        int cnt = min(32, re - i0);
        for (int j = 0; j < cnt; j++) {
            int s = __shfl_sync(0xFFFFFFFFu, s_l, j);
            float a = __ldg(EX + (size_t)(i0 + j) * NH + head) * inv_dn;
            const float4* hp = (const float4*)(T + (size_t)s * FDIM + lane * 16);
            float4 v0 = hp[0], v1 = hp[1], v2 = hp[2], v3 = hp[3];
            acc[0]  += a * v0.x; acc[1]  += a * v0.y; acc[2]  += a * v0.z; acc[3]  += a * v0.w;
            acc[4]  += a * v1.x; acc[5]  += a * v1.y; acc[6]  += a * v1.z; acc[7]  += a * v1.w;
            acc[8]  += a * v2.x; acc[9]  += a * v2.y; acc[10] += a * v2.z; acc[11] += a * v2.w;
            acc[12] += a * v3.x; acc[13] += a * v3.y; acc[14] += a * v3.z; acc[15] += a * v3.w;
        }
    }

    if (MODE == 0) {
        uint32_t ph[8], pl[8];
#pragma unroll
        for (int j = 0; j < 8; j++) {
            float va = fmaxf(acc[j * 2 + 0], 0.f);
            float vb = fmaxf(acc[j * 2 + 1], 0.f);
            __nv_bfloat16 ha = __float2bfloat16_rn(va);
            __nv_bfloat16 hb = __float2bfloat16_rn(vb);
            __nv_bfloat16 la = __float2bfloat16_rn(va - __bfloat162float(ha));
            __nv_bfloat16 lb = __float2bfloat16_rn(vb - __bfloat162float(hb));
            __nv_bfloat162 hh(ha, hb), ll(la, lb);
            ph[j] = *(uint32_t*)&hh;
            pl[j] = *(uint32_t*)&ll;
        }
        size_t off = (size_t)t * FDIM + lane * 16;
        *(uint4*)(Ahi + off)     = make_uint4(ph[0], ph[1], ph[2], ph[3]);
        *(uint4*)(Ahi + off + 8) = make_uint4(ph[4], ph[5], ph[6], ph[7]);
        *(uint4*)(Alo + off)     = make_uint4(pl[0], pl[1], pl[2], pl[3]);
        *(uint4*)(Alo + off + 8) = make_uint4(pl[4], pl[5], pl[6], pl[7]);
    } else {
        float r[16];
#pragma unroll
        for (int j = 0; j < 16; j++) {
            r[j] = fmaxf(acc[j], 0.f);
            r[j] += __shfl_xor_sync(0xFFFFFFFFu, r[j], 8);
            r[j] += __shfl_xor_sync(0xFFFFFFFFu, r[j], 16);
        }
        if (lane < 8) {
            float* op = out + (size_t)t * HD + lane * 16;
#pragma unroll
            for (int j = 0; j < 4; j++)
                *(float4*)(op + j * 4) = make_float4(0.25f * r[j * 4 + 0], 0.25f * r[j * 4 + 1],
                                                     0.25f * r[j * 4 + 2], 0.25f * r[j * 4 + 3]);
        }
    }
}

// ---------------- launch ----------------
extern "C" void kernel_launch(void* const* d_in, const int* in_sizes, int n_in,
                              void* d_out, int out_size) {
    const float* x   = (const float*)d_in[0];
    const int*   src = (const int*)d_in[1];
    const int*   dst = (const int*)d_in[2];
    const float* W0  = (const float*)d_in[3];
    const float* al0 = (const float*)d_in[4];
    const float* ar0 = (const float*)d_in[5];
    const float* W1  = (const float*)d_in[6];
    const float* al1 = (const float*)d_in[7];
    const float* ar1 = (const float*)d_in[8];
    float* out = (float*)d_out;

    float *T, *el, *er, *EX;
    __nv_bfloat16 *Ahi, *Alo, *Whi, *Wlo;
    int *deg, *rowptr, *cursor, *csrc;
    cudaGetSymbolAddress((void**)&T, g_T);
    cudaGetSymbolAddress((void**)&el, g_el);
    cudaGetSymbolAddress((void**)&er, g_er);
    cudaGetSymbolAddress((void**)&EX, g_EX);
    cudaGetSymbolAddress((void**)&Ahi, g_Ahi);
    cudaGetSymbolAddress((void**)&Alo, g_Alo);
    cudaGetSymbolAddress((void**)&Whi, g_Whi);
    cudaGetSymbolAddress((void**)&Wlo, g_Wlo);
    cudaGetSymbolAddress((void**)&deg, g_deg);
    cudaGetSymbolAddress((void**)&rowptr, g_rowptr);
    cudaGetSymbolAddress((void**)&cursor, g_cursor);
    cudaGetSymbolAddress((void**)&csrc, g_csrc);

    cudaFuncSetAttribute(hmma_gemm<IN_DIM>, cudaFuncAttributeMaxDynamicSharedMemorySize, GS_TOTAL);
    cudaFuncSetAttribute(hmma_gemm<FDIM>,   cudaFuncAttributeMaxDynamicSharedMemorySize, GS_TOTAL);

    dim3 gemmGrid(FDIM / 128, (NNODES + 127) / 128);   // (4, 391)
    int elerBlocks = (NNODES * NH + 7) / 8;
    int aggBlocks  = (NNODES + 7) / 8;
    int edgeBlocks = (NEDGES + 255) / 256;

    // ---------------- CSR build (reused by both layers) ----------------
    zero_int_kernel<<<(NNODES + 255) / 256, 256>>>(deg, NNODES);
    hist_kernel<<<edgeBlocks, 256>>>(dst, deg);
    scan_kernel<<<1, 1024>>>(deg, rowptr, cursor);
    scatter_kernel<<<edgeBlocks, 256>>>(src, dst, cursor, csrc);

    // ---------------- layer 0 ----------------
    {
        size_t n4 = (size_t)NNODES * IN_DIM / 4;
        convA_kernel<<<(unsigned)((n4 + 255) / 256), 256>>>(x, Ahi, Alo, n4);
        convW_kernel<<<(FDIM * IN_DIM + 255) / 256, 256>>>(W0, Whi, Wlo, IN_DIM);
        hmma_gemm<IN_DIM><<<gemmGrid, 256, GS_TOTAL>>>(Ahi, Alo, Whi, Wlo, T, NNODES);
    }
    eler_kernel<<<elerBlocks, 256>>>(T, al0, ar0, el, er);
    agg_kernel<0><<<aggBlocks, 256>>>(rowptr, csrc, el, er, T, EX, Ahi, Alo, nullptr);

    // ---------------- layer 1 ----------------
    {
        convW_kernel<<<(FDIM * FDIM + 255) / 256, 256>>>(W1, Whi, Wlo, FDIM);
        hmma_gemm<FDIM><<<gemmGrid, 256, GS_TOTAL>>>(Ahi, Alo, Whi, Wlo, T, NNODES);
    }
    eler_kernel<<<elerBlocks, 256>>>(T, al1, ar1, el, er);
    agg_kernel<1><<<aggBlocks, 256>>>(rowptr, csrc, el, er, T, EX, nullptr, nullptr, out);
}

// round 7
// speedup vs baseline: 3.9058x; 1.2158x over previous
#include <cuda_runtime.h>
#include <cuda_bf16.h>
#include <cstdint>

// Problem constants
#define NNODES 50000
#define NEDGES 600000
#define IN_DIM 256
#define NH     4
#define HD     128
#define FDIM   (NH*HD)     // 512
#define NEG_SLOPE 0.2f

// ---------------- scratch (static __device__ — no allocations allowed) ----------------
__device__ float g_T[(size_t)NNODES * FDIM];     // h = x@W (per layer)
__device__ float g_el[NNODES * NH];
__device__ float g_er[NNODES * NH];
__device__ float g_EX[(size_t)NH * NEDGES];      // exp(e), head-major [head][edge]
__device__ __nv_bfloat16 g_Ahi[(size_t)NNODES * FDIM];
__device__ __nv_bfloat16 g_Alo[(size_t)NNODES * FDIM];
__device__ __nv_bfloat16 g_Whi[(size_t)FDIM * FDIM];   // W^T [N, K] bf16 hi
__device__ __nv_bfloat16 g_Wlo[(size_t)FDIM * FDIM];   // W^T [N, K] bf16 lo
// CSR scratch
__device__ int g_deg[NNODES];
__device__ int g_rowptr[NNODES + 1];
__device__ int g_cursor[NNODES];
__device__ int g_csrc[NEDGES];

// ---------------- small utils ----------------
__global__ void zero_int_kernel(int* p, int n) {
    int i = blockIdx.x * blockDim.x + threadIdx.x;
    if (i < n) p[i] = 0;
}

__global__ void hist_kernel(const int* __restrict__ dst, int* __restrict__ deg) {
    int e = blockIdx.x * blockDim.x + threadIdx.x;
    if (e < NEDGES) atomicAdd(&deg[dst[e]], 1);
}

// single-block Hillis-Steele scan over NNODES, emits rowptr (exclusive) + cursor copy
__global__ __launch_bounds__(1024) void scan_kernel(const int* __restrict__ deg,
                                                    int* __restrict__ rowptr,
                                                    int* __restrict__ cursor) {
    __shared__ int sA[1024], sB[1024];
    int tid = threadIdx.x;
    int carry = 0;
    for (int base = 0; base < NNODES; base += 1024) {
        int i = base + tid;
        int v = (i < NNODES) ? deg[i] : 0;
        sA[tid] = v;
        __syncthreads();
        int* in = sA; int* out = sB;
#pragma unroll
        for (int off = 1; off < 1024; off <<= 1) {
            int x = in[tid];
            if (tid >= off) x += in[tid - off];
            out[tid] = x;
            __syncthreads();
            int* t = in; in = out; out = t;
        }
        int incl = in[tid];
        int excl = incl - v;
        if (i < NNODES) { rowptr[i] = carry + excl; cursor[i] = carry + excl; }
        int total = in[1023];
        __syncthreads();
        carry += total;
    }
    if (tid == 0) rowptr[NNODES] = carry;
}

__global__ void scatter_kernel(const int* __restrict__ src, const int* __restrict__ dst,
                               int* __restrict__ cursor, int* __restrict__ csrc) {
    int e = blockIdx.x * blockDim.x + threadIdx.x;
    if (e >= NEDGES) return;
    int pos = atomicAdd(&cursor[dst[e]], 1);
    csrc[pos] = src[e];
}

// ---------------- fp32 -> bf16 hi/lo split (element-wise) ----------------
__global__ void convA_kernel(const float* __restrict__ in,
                             __nv_bfloat16* __restrict__ hi,
                             __nv_bfloat16* __restrict__ lo, size_t n4) {
    size_t i = (size_t)blockIdx.x * blockDim.x + threadIdx.x;
    if (i >= n4) return;
    float4 v = ((const float4*)in)[i];
    __nv_bfloat16 h0 = __float2bfloat16_rn(v.x), h1 = __float2bfloat16_rn(v.y);
    __nv_bfloat16 h2 = __float2bfloat16_rn(v.z), h3 = __float2bfloat16_rn(v.w);
    __nv_bfloat16 l0 = __float2bfloat16_rn(v.x - __bfloat162float(h0));
    __nv_bfloat16 l1 = __float2bfloat16_rn(v.y - __bfloat162float(h1));
    __nv_bfloat16 l2 = __float2bfloat16_rn(v.z - __bfloat162float(h2));
    __nv_bfloat16 l3 = __float2bfloat16_rn(v.w - __bfloat162float(h3));
    ((__nv_bfloat162*)hi)[i * 2 + 0] = __nv_bfloat162(h0, h1);
    ((__nv_bfloat162*)hi)[i * 2 + 1] = __nv_bfloat162(h2, h3);
    ((__nv_bfloat162*)lo)[i * 2 + 0] = __nv_bfloat162(l0, l1);
    ((__nv_bfloat162*)lo)[i * 2 + 1] = __nv_bfloat162(l2, l3);
}

// ---------------- W[K,512] -> W^T[512,K] bf16 hi/lo ----------------
__global__ void convW_kernel(const float* __restrict__ W,
                             __nv_bfloat16* __restrict__ hi,
                             __nv_bfloat16* __restrict__ lo, int K) {
    int idx = blockIdx.x * blockDim.x + threadIdx.x;
    if (idx >= FDIM * K) return;
    int n = idx / K, k = idx - n * K;
    float v = W[(size_t)k * FDIM + n];
    __nv_bfloat16 h = __float2bfloat16_rn(v);
    hi[idx] = h;
    lo[idx] = __float2bfloat16_rn(v - __bfloat162float(h));
}

// ---------------- HMMA GEMM with cp.async 2-stage pipeline (unchanged from R6) ----------------
#define MMA_BF16(d, a, b)                                                            \
    asm volatile("mma.sync.aligned.m16n8k16.row.col.f32.bf16.bf16.f32 "              \
        "{%0,%1,%2,%3}, {%4,%5,%6,%7}, {%8,%9}, {%0,%1,%2,%3};"                      \
        : "+f"((d)[0]), "+f"((d)[1]), "+f"((d)[2]), "+f"((d)[3])                     \
        : "r"((a)[0]), "r"((a)[1]), "r"((a)[2]), "r"((a)[3]),                        \
          "r"((b)[0]), "r"((b)[1]))

__device__ __forceinline__ void cp16(uint32_t d, const void* g, int sz) {
    asm volatile("cp.async.cg.shared.global [%0], [%1], 16, %2;" :: "r"(d), "l"(g), "r"(sz));
}
__device__ __forceinline__ void cp_commit() { asm volatile("cp.async.commit_group;" ::: "memory"); }
template <int N>
__device__ __forceinline__ void cp_wait() { asm volatile("cp.async.wait_group %0;" :: "n"(N) : "memory"); }

static constexpr int GS_BUF   = 10240;       // 128 rows * 40 elems * 2B
static constexpr int GS_STAGE = 4 * GS_BUF;  // Ah, Al, Bh, Bl
static constexpr int GS_TOTAL = 2 * GS_STAGE;  // 81920

template <int K>
__global__ __launch_bounds__(256) void hmma_gemm(const __nv_bfloat16* __restrict__ Ahi,
                                                 const __nv_bfloat16* __restrict__ Alo,
                                                 const __nv_bfloat16* __restrict__ Bhi,
                                                 const __nv_bfloat16* __restrict__ Blo,
                                                 float* __restrict__ C, int M) {
    extern __shared__ char smem[];
    uint32_t sbase;
    asm("{ .reg .u64 t; cvta.to.shared.u64 t, %1; cvt.u32.u64 %0, t; }" : "=r"(sbase) : "l"(smem));

    int tid = threadIdx.x;
    int lane = tid & 31;
    int wid = tid >> 5;
    int wr = wid & 3;
    int wc = wid >> 2;
    int gr4 = lane >> 2;
    int tig = lane & 3;

    int row0 = blockIdx.y * 128;
    int col0 = blockIdx.x * 128;

    const __nv_bfloat16* gsrc[4] = { Ahi, Alo, Bhi, Blo };

    auto load_stage = [&](int kt, int st) {
        int k0 = kt * 32;
#pragma unroll
        for (int j = 0; j < 8; j++) {
            const int buf = j >> 1;
            int rem = (j & 1) * 256 + tid;
            int r = rem >> 2, c = (rem & 3) * 8;
            uint32_t doff = sbase + st * GS_STAGE + buf * GS_BUF + (r * 40 + c) * 2;
            int gr = (buf < 2) ? (row0 + r) : (col0 + r);
            const void* gp = gsrc[buf] + (size_t)gr * K + k0 + c;
            int sz = (buf < 2 && gr >= M) ? 0 : 16;
            cp16(doff, gp, sz);
        }
    };

    float acc[2][8][4];
#pragma unroll
    for (int mt = 0; mt < 2; mt++)
#pragma unroll
        for (int nt = 0; nt < 8; nt++)
#pragma unroll
            for (int q = 0; q < 4; q++) acc[mt][nt][q] = 0.f;

    const int NK = K / 32;
    load_stage(0, 0);
    cp_commit();

#pragma unroll 1
    for (int kt = 0; kt < NK; kt++) {
        int st = kt & 1;
        if (kt + 1 < NK) { load_stage(kt + 1, st ^ 1); cp_commit(); cp_wait<1>(); }
        else            { cp_wait<0>(); }
        __syncthreads();

        const __nv_bfloat16* pAh = (const __nv_bfloat16*)(smem + st * GS_STAGE);
        const __nv_bfloat16* pAl = (const __nv_bfloat16*)(smem + st * GS_STAGE + GS_BUF);
        const __nv_bfloat16* pBh = (const __nv_bfloat16*)(smem + st * GS_STAGE + 2 * GS_BUF);
        const __nv_bfloat16* pBl = (const __nv_bfloat16*)(smem + st * GS_STAGE + 3 * GS_BUF);

#pragma unroll
        for (int ks = 0; ks < 2; ks++) {
            int kb = ks * 16;
            uint32_t ah[2][4], al[2][4];
#pragma unroll
            for (int mt = 0; mt < 2; mt++) {
                int mr = wr * 32 + mt * 16 + gr4;
                ah[mt][0] = *(const uint32_t*)(pAh + mr * 40 + kb + tig * 2);
                ah[mt][1] = *(const uint32_t*)(pAh + (mr + 8) * 40 + kb + tig * 2);
                ah[mt][2] = *(const uint32_t*)(pAh + mr * 40 + kb + 8 + tig * 2);
                ah[mt][3] = *(const uint32_t*)(pAh + (mr + 8) * 40 + kb + 8 + tig * 2);
                al[mt][0] = *(const uint32_t*)(pAl + mr * 40 + kb + tig * 2);
                al[mt][1] = *(const uint32_t*)(pAl + (mr + 8) * 40 + kb + tig * 2);
                al[mt][2] = *(const uint32_t*)(pAl + mr * 40 + kb + 8 + tig * 2);
                al[mt][3] = *(const uint32_t*)(pAl + (mr + 8) * 40 + kb + 8 + tig * 2);
            }
#pragma unroll
            for (int nt = 0; nt < 8; nt++) {
                int nc = wc * 64 + nt * 8 + gr4;
                uint32_t bh[2], bl[2];
                bh[0] = *(const uint32_t*)(pBh + nc * 40 + kb + tig * 2);
                bh[1] = *(const uint32_t*)(pBh + nc * 40 + kb + 8 + tig * 2);
                bl[0] = *(const uint32_t*)(pBl + nc * 40 + kb + tig * 2);
                bl[1] = *(const uint32_t*)(pBl + nc * 40 + kb + 8 + tig * 2);
#pragma unroll
                for (int mt = 0; mt < 2; mt++) {
                    MMA_BF16(acc[mt][nt], ah[mt], bh);
                    MMA_BF16(acc[mt][nt], ah[mt], bl);
                    MMA_BF16(acc[mt][nt], al[mt], bh);
                }
            }
        }
        __syncthreads();
    }

#pragma unroll
    for (int mt = 0; mt < 2; mt++) {
        int r0 = row0 + wr * 32 + mt * 16 + gr4;
#pragma unroll
        for (int nt = 0; nt < 8; nt++) {
            int cc = col0 + wc * 64 + nt * 8 + tig * 2;
            if (r0 < M)
                *(float2*)(C + (size_t)r0 * FDIM + cc) = make_float2(acc[mt][nt][0], acc[mt][nt][1]);
            if (r0 + 8 < M)
                *(float2*)(C + (size_t)(r0 + 8) * FDIM + cc) = make_float2(acc[mt][nt][2], acc[mt][nt][3]);
        }
    }
}

// ---------------- el/er: per (node, head) dot products ----------------
__global__ void eler_kernel(const float* __restrict__ T,
                            const float* __restrict__ al,
                            const float* __restrict__ ar,
                            float* __restrict__ el, float* __restrict__ er) {
    int warp = (blockIdx.x * blockDim.x + threadIdx.x) >> 5;
    int lane = threadIdx.x & 31;
    if (warp >= NNODES * NH) return;
    int n = warp >> 2;
    int h = warp & 3;

    const float4 tv = *(const float4*)(T + (size_t)n * FDIM + h * HD + lane * 4);
    const float4 av = *(const float4*)(al + h * HD + lane * 4);
    const float4 rv = *(const float4*)(ar + h * HD + lane * 4);

    float sl = tv.x * av.x + tv.y * av.y + tv.z * av.z + tv.w * av.w;
    float sr = tv.x * rv.x + tv.y * rv.y + tv.z * rv.z + tv.w * rv.w;
#pragma unroll
    for (int o = 16; o > 0; o >>= 1) {
        sl += __shfl_xor_sync(0xFFFFFFFFu, sl, o);
        sr += __shfl_xor_sync(0xFFFFFFFFu, sr, o);
    }
    if (lane == 0) { el[warp] = sl; er[warp] = sr; }
}

__device__ __forceinline__ float lrelu_exp(float v) {
    v = v > 0.f ? v : NEG_SLOPE * v;
    return __expf(v);
}

// ---------------- CSR aggregation: one warp per (node, head) ----------------
// Warps of the same node live in the same block (8 warps = 2 nodes per block).
// Phase 1: exp(e) per edge -> EX[head][edge] (coalesced), denom reduce.
// Phase 2: lane owns 4 features of its head; per edge: broadcast EX + float4 gather.
// MODE 0: relu + bf16 hi/lo stores. MODE 1: head-mean via smem reduction.
template <int MODE>
__global__ __launch_bounds__(256) void agg_kernel(const int* __restrict__ rowptr,
                                                  const int* __restrict__ csrc,
                                                  const float* __restrict__ el,
                                                  const float* __restrict__ er,
                                                  const float* __restrict__ T,
                                                  float* __restrict__ EX,
                                                  __nv_bfloat16* __restrict__ Ahi,
                                                  __nv_bfloat16* __restrict__ Alo,
                                                  float* __restrict__ out) {
    __shared__ float sred[2][FDIM];   // MODE 1 only
    int gw = (blockIdx.x * blockDim.x + threadIdx.x) >> 5;
    int lane = threadIdx.x & 31;
    int t = gw >> 2;
    int head = gw & 3;

    if (t < NNODES) {
        int rs = rowptr[t], re = rowptr[t + 1];
        float er_own = __ldg(er + (size_t)t * NH + head);
        float* EXp = EX + (size_t)head * NEDGES;

        // phase 1: exp per edge (own head), coalesced store, denom reduce
        float d = 0.f;
        for (int i = rs + lane; i < re; i += 32) {
            int s = __ldg(csrc + i);
            float ex = lrelu_exp(__ldg(el + (size_t)s * NH + head) + er_own);
            EXp[i] = ex;
            d += ex;
        }
#pragma unroll
        for (int o = 16; o > 0; o >>= 1) d += __shfl_xor_sync(0xFFFFFFFFu, d, o);
        float inv_dn = (d > 0.f) ? (1.f / d) : 0.f;
        __syncwarp();

        // phase 2: acc over edges; lane owns features [head*128 + lane*4, +4)
        float4 acc = make_float4(0.f, 0.f, 0.f, 0.f);
        const float* Tb = T + head * HD + lane * 4;
        for (int i0 = rs; i0 < re; i0 += 32) {
            int s_l = (i0 + lane < re) ? __ldg(csrc + i0 + lane) : 0;
            int cnt = min(32, re - i0);
            int j = 0;
            for (; j + 1 < cnt; j += 2) {
                int s0 = __shfl_sync(0xFFFFFFFFu, s_l, j);
                int s1 = __shfl_sync(0xFFFFFFFFu, s_l, j + 1);
                float a0 = EXp[i0 + j] * inv_dn;
                float a1 = EXp[i0 + j + 1] * inv_dn;
                float4 v0 = *(const float4*)(Tb + (size_t)s0 * FDIM);
                float4 v1 = *(const float4*)(Tb + (size_t)s1 * FDIM);
                acc.x += a0 * v0.x + a1 * v1.x;
                acc.y += a0 * v0.y + a1 * v1.y;
                acc.z += a0 * v0.z + a1 * v1.z;
                acc.w += a0 * v0.w + a1 * v1.w;
            }
            if (j < cnt) {
                int s0 = __shfl_sync(0xFFFFFFFFu, s_l, j);
                float a0 = EXp[i0 + j] * inv_dn;
                float4 v0 = *(const float4*)(Tb + (size_t)s0 * FDIM);
                acc.x += a0 * v0.x;
                acc.y += a0 * v0.y;
                acc.z += a0 * v0.z;
                acc.w += a0 * v0.w;
            }
        }

        acc.x = fmaxf(acc.x, 0.f);
        acc.y = fmaxf(acc.y, 0.f);
        acc.z = fmaxf(acc.z, 0.f);
        acc.w = fmaxf(acc.w, 0.f);

        if (MODE == 0) {
            __nv_bfloat16 h0 = __float2bfloat16_rn(acc.x), h1 = __float2bfloat16_rn(acc.y);
            __nv_bfloat16 h2 = __float2bfloat16_rn(acc.z), h3 = __float2bfloat16_rn(acc.w);
            __nv_bfloat16 l0 = __float2bfloat16_rn(acc.x - __bfloat162float(h0));
            __nv_bfloat16 l1 = __float2bfloat16_rn(acc.y - __bfloat162float(h1));
            __nv_bfloat16 l2 = __float2bfloat16_rn(acc.z - __bfloat162float(h2));
            __nv_bfloat16 l3 = __float2bfloat16_rn(acc.w - __bfloat162float(h3));
            size_t off = (size_t)t * FDIM + head * HD + lane * 4;
            __nv_bfloat162 hh0(h0, h1), hh1(h2, h3), ll0(l0, l1), ll1(l2, l3);
            uint32_t ph0 = *(uint32_t*)&hh0, ph1 = *(uint32_t*)&hh1;
            uint32_t pl0 = *(uint32_t*)&ll0, pl1 = *(uint32_t*)&ll1;
            *(uint2*)(Ahi + off) = make_uint2(ph0, ph1);
            *(uint2*)(Alo + off) = make_uint2(pl0, pl1);
        } else {
            int nl = (threadIdx.x >> 5) >> 2;   // node slot in block (0/1)
            *(float4*)&sred[nl][head * HD + lane * 4] = acc;
        }
    }

    if (MODE == 1) {
        __syncthreads();
        int tid = threadIdx.x;
        int nl = tid >> 7;            // 0/1
        int dch = tid & 127;          // feature
        int node = blockIdx.x * 2 + nl;
        if (node < NNODES) {
            float v = sred[nl][dch] + sred[nl][HD + dch] + sred[nl][2 * HD + dch] + sred[nl][3 * HD + dch];
            out[(size_t)node * HD + dch] = 0.25f * v;
        }
    }
}

// ---------------- launch ----------------
extern "C" void kernel_launch(void* const* d_in, const int* in_sizes, int n_in,
                              void* d_out, int out_size) {
    const float* x   = (const float*)d_in[0];
    const int*   src = (const int*)d_in[1];
    const int*   dst = (const int*)d_in[2];
    const float* W0  = (const float*)d_in[3];
    const float* al0 = (const float*)d_in[4];
    const float* ar0 = (const float*)d_in[5];
    const float* W1  = (const float*)d_in[6];
    const float* al1 = (const float*)d_in[7];
    const float* ar1 = (const float*)d_in[8];
    float* out = (float*)d_out;

    float *T, *el, *er, *EX;
    __nv_bfloat16 *Ahi, *Alo, *Whi, *Wlo;
    int *deg, *rowptr, *cursor, *csrc;
    cudaGetSymbolAddress((void**)&T, g_T);
    cudaGetSymbolAddress((void**)&el, g_el);
    cudaGetSymbolAddress((void**)&er, g_er);
    cudaGetSymbolAddress((void**)&EX, g_EX);
    cudaGetSymbolAddress((void**)&Ahi, g_Ahi);
    cudaGetSymbolAddress((void**)&Alo, g_Alo);
    cudaGetSymbolAddress((void**)&Whi, g_Whi);
    cudaGetSymbolAddress((void**)&Wlo, g_Wlo);
    cudaGetSymbolAddress((void**)&deg, g_deg);
    cudaGetSymbolAddress((void**)&rowptr, g_rowptr);
    cudaGetSymbolAddress((void**)&cursor, g_cursor);
    cudaGetSymbolAddress((void**)&csrc, g_csrc);

    cudaFuncSetAttribute(hmma_gemm<IN_DIM>, cudaFuncAttributeMaxDynamicSharedMemorySize, GS_TOTAL);
    cudaFuncSetAttribute(hmma_gemm<FDIM>,   cudaFuncAttributeMaxDynamicSharedMemorySize, GS_TOTAL);

    dim3 gemmGrid(FDIM / 128, (NNODES + 127) / 128);   // (4, 391)
    int elerBlocks = (NNODES * NH + 7) / 8;
    int aggBlocks  = (NNODES * NH + 7) / 8;             // warp per (node, head)
    int edgeBlocks = (NEDGES + 255) / 256;

    // ---------------- fork CSR build onto side stream ----------------
    cudaStream_t s1;
    cudaStreamCreateWithFlags(&s1, cudaStreamNonBlocking);
    cudaEvent_t ev0, ev1;
    cudaEventCreateWithFlags(&ev0, cudaEventDisableTiming);
    cudaEventCreateWithFlags(&ev1, cudaEventDisableTiming);

    cudaEventRecord(ev0, 0);
    cudaStreamWaitEvent(s1, ev0, 0);
    zero_int_kernel<<<(NNODES + 255) / 256, 256, 0, s1>>>(deg, NNODES);
    hist_kernel<<<edgeBlocks, 256, 0, s1>>>(dst, deg);
    scan_kernel<<<1, 1024, 0, s1>>>(deg, rowptr, cursor);
    scatter_kernel<<<edgeBlocks, 256, 0, s1>>>(src, dst, cursor, csrc);
    cudaEventRecord(ev1, s1);

    // ---------------- layer 0 (main stream, overlaps CSR) ----------------
    {
        size_t n4 = (size_t)NNODES * IN_DIM / 4;
        convA_kernel<<<(unsigned)((n4 + 255) / 256), 256>>>(x, Ahi, Alo, n4);
        convW_kernel<<<(FDIM * IN_DIM + 255) / 256, 256>>>(W0, Whi, Wlo, IN_DIM);
        hmma_gemm<IN_DIM><<<gemmGrid, 256, GS_TOTAL>>>(Ahi, Alo, Whi, Wlo, T, NNODES);
    }
    eler_kernel<<<elerBlocks, 256>>>(T, al0, ar0, el, er);

    cudaStreamWaitEvent(0, ev1, 0);   // join: agg needs CSR
    agg_kernel<0><<<aggBlocks, 256>>>(rowptr, csrc, el, er, T, EX, Ahi, Alo, nullptr);

    // ---------------- layer 1 ----------------
    {
        convW_kernel<<<(FDIM * FDIM + 255) / 256, 256>>>(W1, Whi, Wlo, FDIM);
        hmma_gemm<FDIM><<<gemmGrid, 256, GS_TOTAL>>>(Ahi, Alo, Whi, Wlo, T, NNODES);
    }
    eler_kernel<<<elerBlocks, 256>>>(T, al1, ar1, el, er);
    agg_kernel<1><<<aggBlocks, 256>>>(rowptr, csrc, el, er, T, EX, nullptr, nullptr, out);
}